// round 14
// baseline (speedup 1.0000x reference)
#include <cuda_runtime.h>
#include <cuda_bf16.h>
#include <cuda_fp16.h>
#include <cstdint>
#include <math.h>

// Problem constants
constexpr int B_   = 2;
constexpr int T_   = 1024;
constexpr int C_   = 4096;
constexpr int HQ   = 32;
constexpr int HKV  = 8;
constexpr int D_   = 128;
constexpr int G_   = 4;
constexpr int CT_  = 4096;
constexpr int NQKV = C_ + 2 * HKV * D_;  // 6144 fused QKV output width

// fp32 scratch: fused qkv output [M, 6144]
__device__ float g_qkv[(size_t)B_ * T_ * NQKV];

// bf16 hi/lo scratch
__device__ __nv_bfloat16 g_xh  [(size_t)B_ * T_ * C_];
__device__ __nv_bfloat16 g_xl  [(size_t)B_ * T_ * C_];
__device__ __nv_bfloat16 g_wqkvh[(size_t)NQKV * C_];
__device__ __nv_bfloat16 g_wqkvl[(size_t)NQKV * C_];
__device__ __nv_bfloat16 g_woh [(size_t)C_ * C_];
__device__ __nv_bfloat16 g_wol [(size_t)C_ * C_];
__device__ __nv_bfloat16 g_cth [(size_t)B_ * T_ * C_];
__device__ __nv_bfloat16 g_ctl [(size_t)B_ * T_ * C_];

// bf16 hi/lo attention operands
__device__ __nv_bfloat16 g_qah[(size_t)B_ * T_ * HQ * D_];
__device__ __nv_bfloat16 g_qal[(size_t)B_ * T_ * HQ * D_];
__device__ __nv_bfloat16 g_kch[(size_t)B_ * CT_ * HKV * D_];
__device__ __nv_bfloat16 g_kcl[(size_t)B_ * CT_ * HKV * D_];
__device__ __nv_bfloat16 g_vch[(size_t)B_ * CT_ * HKV * D_];
__device__ __nv_bfloat16 g_vcl[(size_t)B_ * CT_ * HKV * D_];

__device__ __forceinline__ uint32_t smem_u32(const void* p) {
  uint32_t a;
  asm("{ .reg .u64 t; cvta.to.shared.u64 t, %1; cvt.u32.u64 %0, t; }"
      : "=r"(a) : "l"(p));
  return a;
}

__device__ __forceinline__ void ldsm4(uint32_t* r, uint32_t addr) {
  asm volatile("ldmatrix.sync.aligned.m8n8.x4.shared.b16 {%0,%1,%2,%3}, [%4];"
               : "=r"(r[0]), "=r"(r[1]), "=r"(r[2]), "=r"(r[3]) : "r"(addr));
}

__device__ __forceinline__ void ldsm4t(uint32_t* r, uint32_t addr) {
  asm volatile("ldmatrix.sync.aligned.m8n8.x4.trans.shared.b16 {%0,%1,%2,%3}, [%4];"
               : "=r"(r[0]), "=r"(r[1]), "=r"(r[2]), "=r"(r[3]) : "r"(addr));
}

__device__ __forceinline__ void mma16816(float* d, const uint32_t* a,
                                         uint32_t b0, uint32_t b1) {
  asm volatile(
      "mma.sync.aligned.m16n8k16.row.col.f32.bf16.bf16.f32 "
      "{%0,%1,%2,%3},{%4,%5,%6,%7},{%8,%9},{%0,%1,%2,%3};"
      : "+f"(d[0]), "+f"(d[1]), "+f"(d[2]), "+f"(d[3])
      : "r"(a[0]), "r"(a[1]), "r"(a[2]), "r"(a[3]), "r"(b0), "r"(b1));
}

__device__ __forceinline__ void cp_async16(uint32_t dst, const void* src) {
  asm volatile("cp.async.cg.shared.global [%0], [%1], 16;"
               :: "r"(dst), "l"(src) : "memory");
}

__device__ __forceinline__ void split2(float a0, float a1, __nv_bfloat162& h,
                                       __nv_bfloat162& l) {
  h = __float22bfloat162_rn(make_float2(a0, a1));
  l = __float22bfloat162_rn(make_float2(a0 - __bfloat162float(h.x),
                                        a1 - __bfloat162float(h.y)));
}

// ---------------------------------------------------------------------------
// fp32 -> bf16 hi/lo split (elementwise)
// ---------------------------------------------------------------------------
__global__ void cvt_kernel(const float4* __restrict__ in,
                           __nv_bfloat162* __restrict__ hi,
                           __nv_bfloat162* __restrict__ lo, int n4) {
  int i = blockIdx.x * blockDim.x + threadIdx.x;
  if (i >= n4) return;
  float4 v = in[i];
  __nv_bfloat162 h0, l0, h1, l1;
  split2(v.x, v.y, h0, l0);
  split2(v.z, v.w, h1, l1);
  hi[2 * i] = h0; hi[2 * i + 1] = h1;
  lo[2 * i] = l0; lo[2 * i + 1] = l1;
}

// ---------------------------------------------------------------------------
// Fused rope + split + pack for fresh q/k/v, reading from the fused
// qkv buffer [M, 6144] (q at col 0, k at 4096, v at 5120).
// ---------------------------------------------------------------------------
__global__ void rope_pack_kernel(const float* __restrict__ qkv,
                                 const int* __restrict__ spp,
                                 __nv_bfloat162* __restrict__ qh,
                                 __nv_bfloat162* __restrict__ ql,
                                 __nv_bfloat162* __restrict__ kh,
                                 __nv_bfloat162* __restrict__ kl,
                                 __nv_bfloat162* __restrict__ vh,
                                 __nv_bfloat162* __restrict__ vl) {
  const int sp = *spp;
  const int M = B_ * T_;
  const int qpairs = M * HQ * 64;
  const int kpairs = M * HKV * 64;
  int idx = blockIdx.x * blockDim.x + threadIdx.x;

  if (idx < qpairs) {
    const int i = idx & 63, h = (idx >> 6) & 31, m = idx >> 11;
    const int t = m % T_;
    const float freq = __expf(-(float)i * (9.210340371976184f / 64.f));
    float s, c;
    sincosf((float)(sp + t) * freq, &s, &c);
    float2 x = *(const float2*)(qkv + (size_t)m * NQKV + h * D_ + 2 * i);
    float o0 = x.x * c - x.y * s, o1 = x.x * s + x.y * c;
    __nv_bfloat162 hh, ll;
    split2(o0, o1, hh, ll);
    qh[idx] = hh; ql[idx] = ll;
    return;
  }
  idx -= qpairs;
  if (idx < kpairs) {
    const int i = idx & 63, kv = (idx >> 6) & 7, m = idx >> 9;
    const int t = m % T_, b = m / T_;
    const float freq = __expf(-(float)i * (9.210340371976184f / 64.f));
    float s, c;
    sincosf((float)(sp + t) * freq, &s, &c);
    float2 x = *(const float2*)(qkv + (size_t)m * NQKV + C_ + kv * D_ + 2 * i);
    float o0 = x.x * c - x.y * s, o1 = x.x * s + x.y * c;
    __nv_bfloat162 hh, ll;
    split2(o0, o1, hh, ll);
    size_t dst = (((size_t)b * CT_ + sp + t) * HKV + kv) * 64 + i;
    kh[dst] = hh; kl[dst] = ll;
    return;
  }
  idx -= kpairs;
  if (idx >= kpairs) return;
  const int i = idx & 63, kv = (idx >> 6) & 7, m = idx >> 9;
  const int t = m % T_, b = m / T_;
  float2 x = *(const float2*)(qkv + (size_t)m * NQKV + C_ + HKV * D_ + kv * D_ + 2 * i);
  __nv_bfloat162 hh, ll;
  split2(x.x, x.y, hh, ll);
  size_t dst = (((size_t)b * CT_ + sp + t) * HKV + kv) * 64 + i;
  vh[dst] = hh; vl[dst] = ll;
}

// ---------------------------------------------------------------------------
// Pack cache K/V (s < sp only) -> bf16 hi/lo concat buffers.
// ---------------------------------------------------------------------------
__global__ void pack_cache_kernel(const float* __restrict__ ck,
                                  const float* __restrict__ cv,
                                  const int* __restrict__ spp,
                                  __nv_bfloat162* __restrict__ kh,
                                  __nv_bfloat162* __restrict__ kl,
                                  __nv_bfloat162* __restrict__ vh,
                                  __nv_bfloat162* __restrict__ vl) {
  const int sp = *spp;
  int idx = blockIdx.x * blockDim.x + threadIdx.x;  // over B*CT*HKV*(D/4)
  int d4 = idx & 31;
  int kv = (idx >> 5) & 7;
  int s  = (idx >> 8) & (CT_ - 1);
  int b  = idx >> 20;
  if (b >= B_ || s >= sp) return;

  size_t src = (((size_t)b * CT_ + s) * HKV + kv) * D_ + d4 * 4;
  size_t dst2 = ((((size_t)b * CT_ + s) * HKV + kv) * D_) / 2 + d4 * 2;

  float4 kx = *(const float4*)(ck + src);
  float4 vx = *(const float4*)(cv + src);
  __nv_bfloat162 h, l;
  split2(kx.x, kx.y, h, l); kh[dst2] = h; kl[dst2] = l;
  split2(kx.z, kx.w, h, l); kh[dst2 + 1] = h; kl[dst2 + 1] = l;
  split2(vx.x, vx.y, h, l); vh[dst2] = h; vl[dst2] = l;
  split2(vx.z, vx.w, h, l); vh[dst2 + 1] = h; vl[dst2 + 1] = l;
}

// ---------------------------------------------------------------------------
// Tensor-core GEMM (verified): C[M,N] = A[M,K]*B[N,K]^T, 3-term split.
// ---------------------------------------------------------------------------
__global__ void __launch_bounds__(256) gemm_mma_kernel(
    const __nv_bfloat16* __restrict__ Ah, const __nv_bfloat16* __restrict__ Al,
    const __nv_bfloat16* __restrict__ Bh, const __nv_bfloat16* __restrict__ Bl,
    float* __restrict__ C, int M, int N, int K) {
  extern __shared__ char sm[];
  const int tid = threadIdx.x, lane = tid & 31, wid = tid >> 5;
  const int bm = blockIdx.y << 7, bn = blockIdx.x << 7;
  const uint32_t sbase = smem_u32(sm);

  const int warp_m = wid >> 2;
  const int warp_n = wid & 3;

  const __nv_bfloat16* srcs[4] = {Ah, Al, Bh, Bl};

  auto issue = [&](int c, int buf) {
    const int k0 = c << 6;
    const int r = tid >> 1;
    const int s0 = (tid & 1) << 2;
#pragma unroll
    for (int m = 0; m < 4; m++) {
      const __nv_bfloat16* g =
          srcs[m] + (size_t)((m < 2 ? bm : bn) + r) * K + k0;
      uint32_t dstb = sbase + buf * 65536 + m * 16384 + r * 128;
      uint32_t rsw = (uint32_t)(r & 7) << 4;
#pragma unroll
      for (int i = 0; i < 4; i++) {
        int seg = s0 + i;
        cp_async16(dstb + ((uint32_t)(seg << 4) ^ rsw), g + seg * 8);
      }
    }
    asm volatile("cp.async.commit_group;" ::: "memory");
  };

  float acc[4][4][4];
#pragma unroll
  for (int i = 0; i < 4; i++)
#pragma unroll
    for (int j = 0; j < 4; j++)
#pragma unroll
      for (int t = 0; t < 4; t++) acc[i][j][t] = 0.f;

  const int l7 = lane & 7, m1b = (lane >> 3) & 1, m2b = lane >> 4;

  const int nch = K >> 6;
  issue(0, 0);
  for (int c = 0; c < nch; c++) {
    const int buf = c & 1;
    if (c + 1 < nch) {
      issue(c + 1, buf ^ 1);
      asm volatile("cp.async.wait_group 1;" ::: "memory");
    } else {
      asm volatile("cp.async.wait_group 0;" ::: "memory");
    }
    __syncthreads();

    const uint32_t bAh = sbase + buf * 65536;
    const uint32_t bAl = bAh + 16384;
    const uint32_t bBh = bAh + 32768;
    const uint32_t bBl = bAh + 49152;

#pragma unroll
    for (int kk = 0; kk < 4; kk++) {
      uint32_t ah[4][4], al[4][4], bh[2][4], bl[2][4];
#pragma unroll
      for (int i = 0; i < 4; i++) {
        int row = warp_m * 64 + i * 16 + l7 + m1b * 8;
        uint32_t bo = (uint32_t)(kk * 32 + m2b * 16) ^ ((uint32_t)(row & 7) << 4);
        uint32_t ro = (uint32_t)row * 128 + bo;
        ldsm4(ah[i], bAh + ro);
        ldsm4(al[i], bAl + ro);
      }
#pragma unroll
      for (int jp = 0; jp < 2; jp++) {
        int row = warp_n * 32 + jp * 16 + l7 + m2b * 8;
        uint32_t bo = (uint32_t)(kk * 32 + m1b * 16) ^ ((uint32_t)(row & 7) << 4);
        uint32_t ro = (uint32_t)row * 128 + bo;
        ldsm4(bh[jp], bBh + ro);
        ldsm4(bl[jp], bBl + ro);
      }
#pragma unroll
      for (int i = 0; i < 4; i++) {
#pragma unroll
        for (int j = 0; j < 4; j++) {
          uint32_t h0 = bh[j >> 1][(j & 1) * 2], h1 = bh[j >> 1][(j & 1) * 2 + 1];
          uint32_t l0 = bl[j >> 1][(j & 1) * 2], l1 = bl[j >> 1][(j & 1) * 2 + 1];
          mma16816(acc[i][j], ah[i], h0, h1);
          mma16816(acc[i][j], ah[i], l0, l1);
          mma16816(acc[i][j], al[i], h0, h1);
        }
      }
    }
    __syncthreads();
  }

  const int rq = lane >> 2, cq = (lane & 3) << 1;
#pragma unroll
  for (int i = 0; i < 4; i++) {
#pragma unroll
    for (int j = 0; j < 4; j++) {
      int row0 = bm + warp_m * 64 + i * 16 + rq;
      int col = bn + warp_n * 32 + j * 8 + cq;
      *(float2*)(C + (size_t)row0 * N + col) =
          make_float2(acc[i][j][0], acc[i][j][1]);
      *(float2*)(C + (size_t)(row0 + 8) * N + col) =
          make_float2(acc[i][j][2], acc[i][j][3]);
    }
  }
}

// ---------------------------------------------------------------------------
// HMMA flash attention: Q-hi fragments in registers (loaded once), Q-lo in
// 32KB smem, 3-stage cp.async KV pipeline (3 x 64KB), f16x2 exp softmax,
// bf16 hi/lo context output. smem total 224KB.
// Layout: [0,32KB) Ql (2 panels x 16KB); stage i at 32KB + i*64KB with
// mats {Kh,Kl,Vh,Vl} x 16KB. Qh staged through stage-2 then overwritten.
// ---------------------------------------------------------------------------
__global__ void __launch_bounds__(256) attn_mma_kernel(
    const __nv_bfloat16* __restrict__ qh_, const __nv_bfloat16* __restrict__ ql_,
    const __nv_bfloat16* __restrict__ kh_, const __nv_bfloat16* __restrict__ kl_,
    const __nv_bfloat16* __restrict__ vh_, const __nv_bfloat16* __restrict__ vl_,
    const int* __restrict__ spp, __nv_bfloat162* __restrict__ cth,
    __nv_bfloat162* __restrict__ ctl) {
  extern __shared__ __align__(1024) char sm[];
  const int sp = *spp;
  const int Stot = sp + T_;
  const int tid = threadIdx.x, lane = tid & 31, w = tid >> 5;
  const int t0 = (gridDim.x - 1 - blockIdx.x) << 5;  // heavy-first
  const int kv = blockIdx.y;
  const int b  = blockIdx.z;
  const uint32_t sb = smem_u32(sm);
  const uint32_t QlB = sb;                  // 32KB
  const uint32_t KV0 = sb + 32768;          // 3 x 64KB stages
  const uint32_t Q2  = KV0 + 2 * 65536;     // Qh staging (stage 2)

  const __nv_bfloat16* kvsrc[4] = {kh_, kl_, vh_, vl_};
  auto issue_kv = [&](int c, int stage) {
    const uint32_t base = KV0 + (uint32_t)stage * 65536;
#pragma unroll
    for (int it = 0; it < 16; it++) {
      int idx = it * 256 + tid;
      int mat = idx >> 10, rem = idx & 1023;
      int row = rem >> 4, seg = rem & 15;
      int s = c * 64 + row;
      if (s > Stot - 1) s = Stot - 1;
      const __nv_bfloat16* g = kvsrc[mat] +
          (((size_t)b * CT_ + s) * HKV + kv) * D_ + seg * 8;
      uint32_t dst = base + mat * 16384 + (seg >> 3) * 8192 + (uint32_t)row * 128 +
          (((uint32_t)(seg & 7) << 4) ^ ((uint32_t)(row & 7) << 4));
      cp_async16(dst, g);
    }
    asm volatile("cp.async.commit_group;" ::: "memory");
  };

  const int nch = (sp + t0 + 31) / 64 + 1;

  // Prologue: Q (hi->stage2 staging, lo->QlB), then kv0, kv1
  {
#pragma unroll
    for (int it = 0; it < 16; it++) {
      int idx = it * 256 + tid;
      int mat = idx >> 11, rem = idx & 2047;
      int row = rem >> 4, seg = rem & 15;
      int t = t0 + (row >> 2), h = (kv << 2) + (row & 3);
      const __nv_bfloat16* src = (mat ? ql_ : qh_) +
          (((size_t)b * T_ + t) * HQ + h) * D_ + seg * 8;
      uint32_t base = mat ? QlB : Q2;
      uint32_t dst = base + (seg >> 3) * 16384 + (uint32_t)row * 128 +
          (((uint32_t)(seg & 7) << 4) ^ ((uint32_t)(row & 7) << 4));
      cp_async16(dst, src);
    }
    asm volatile("cp.async.commit_group;" ::: "memory");
  }
  issue_kv(0, 0);
  if (nch > 1) {
    issue_kv(1, 1);
    asm volatile("cp.async.wait_group 2;" ::: "memory");  // Q retired
  } else {
    asm volatile("cp.async.wait_group 1;" ::: "memory");
  }
  __syncthreads();

  const int wbase = w * 16;
  const int l7 = lane & 7, m1b = (lane >> 3) & 1, m2b = lane >> 4;
  const int r0 = wbase + (lane >> 2);
  const int lim0 = sp + t0 + (r0 >> 2);
  const int lim1 = sp + t0 + ((r0 + 8) >> 2);
  const float scale = 0.08838834764831845f;
  const float L2E = 1.4426950408889634f;
  const int arow = wbase + l7 + m1b * 8;

  // Load Qh fragments into registers (once)
  uint32_t qhf[8][4];
#pragma unroll
  for (int kk = 0; kk < 8; kk++) {
    uint32_t abo = ((uint32_t)((kk & 3) * 32 + m2b * 16)) ^
                   ((uint32_t)(arow & 7) << 4);
    uint32_t aoff = (uint32_t)(kk >> 2) * 16384 + (uint32_t)arow * 128 + abo;
    ldsm4(qhf[kk], Q2 + aoff);
  }
  __syncthreads();  // all warps done reading Q2 before kv2 overwrites it
  if (nch > 2) issue_kv(2, 2);

  float ctxf[16][4];
#pragma unroll
  for (int i = 0; i < 16; i++)
#pragma unroll
    for (int j = 0; j < 4; j++) ctxf[i][j] = 0.f;
  float m0 = -1e30f, m1 = -1e30f, l0 = 0.f, l1 = 0.f;

  for (int c = 0; c < nch; c++) {
    const int stage = c % 3;
    const int rem = nch - 1 - c;
    if (rem == 0) {
      asm volatile("cp.async.wait_group 0;" ::: "memory");
    } else if (rem == 1) {
      asm volatile("cp.async.wait_group 1;" ::: "memory");
    } else {
      asm volatile("cp.async.wait_group 2;" ::: "memory");
    }
    __syncthreads();

    const uint32_t Kh = KV0 + (uint32_t)stage * 65536, Kl = Kh + 16384;
    const uint32_t Vh = Kh + 32768, Vl = Kh + 49152;

    // ---- QK^T (3-term; Qh from regs, Ql from smem) ----
    float sc[8][4];
#pragma unroll
    for (int j = 0; j < 8; j++)
#pragma unroll
      for (int e = 0; e < 4; e++) sc[j][e] = 0.f;

#pragma unroll
    for (int kk = 0; kk < 8; kk++) {
      uint32_t abo = ((uint32_t)((kk & 3) * 32 + m2b * 16)) ^
                     ((uint32_t)(arow & 7) << 4);
      uint32_t aoff = (uint32_t)(kk >> 2) * 16384 + (uint32_t)arow * 128 + abo;
      uint32_t al[4];
      ldsm4(al, QlB + aoff);
#pragma unroll
      for (int jp = 0; jp < 4; jp++) {
        int brow = jp * 16 + l7 + m2b * 8;
        uint32_t bbo = ((uint32_t)((kk & 3) * 32 + m1b * 16)) ^
                       ((uint32_t)(brow & 7) << 4);
        uint32_t boff = (uint32_t)(kk >> 2) * 8192 + (uint32_t)brow * 128 + bbo;
        uint32_t bh[4], bl[4];
        ldsm4(bh, Kh + boff);
        ldsm4(bl, Kl + boff);
        mma16816(sc[jp * 2], qhf[kk], bh[0], bh[1]);
        mma16816(sc[jp * 2], qhf[kk], bl[0], bl[1]);
        mma16816(sc[jp * 2], al, bh[0], bh[1]);
        mma16816(sc[jp * 2 + 1], qhf[kk], bh[2], bh[3]);
        mma16816(sc[jp * 2 + 1], qhf[kk], bl[2], bl[3]);
        mma16816(sc[jp * 2 + 1], al, bh[2], bh[3]);
      }
    }

    // ---- mask + online softmax ----
    const int kbase = c * 64;
    float cm0 = -1e30f, cm1 = -1e30f;
#pragma unroll
    for (int j = 0; j < 8; j++) {
#pragma unroll
      for (int e = 0; e < 2; e++) {
        int key = kbase + j * 8 + 2 * (lane & 3) + e;
        float v0 = sc[j][e] * scale;
        float v1 = sc[j][2 + e] * scale;
        if (key > lim0) v0 = -1e30f;
        if (key > lim1) v1 = -1e30f;
        sc[j][e] = v0; sc[j][2 + e] = v1;
        cm0 = fmaxf(cm0, v0); cm1 = fmaxf(cm1, v1);
      }
    }
    cm0 = fmaxf(cm0, __shfl_xor_sync(0xffffffffu, cm0, 1));
    cm0 = fmaxf(cm0, __shfl_xor_sync(0xffffffffu, cm0, 2));
    cm1 = fmaxf(cm1, __shfl_xor_sync(0xffffffffu, cm1, 1));
    cm1 = fmaxf(cm1, __shfl_xor_sync(0xffffffffu, cm1, 2));
    float mn0 = fmaxf(m0, cm0), mn1 = fmaxf(m1, cm1);
    float s0f = __expf(m0 - mn0), s1f = __expf(m1 - mn1);
    m0 = mn0; m1 = mn1;
    const float m0L = m0 * L2E, m1L = m1 * L2E;

    float ps0 = 0.f, ps1 = 0.f;
    uint32_t pkh[8][2], pkl[8][2];
#pragma unroll
    for (int j = 0; j < 8; j++) {
      float y0 = fmaf(sc[j][0], L2E, -m0L), y1 = fmaf(sc[j][1], L2E, -m0L);
      float y2 = fmaf(sc[j][2], L2E, -m1L), y3 = fmaf(sc[j][3], L2E, -m1L);
      float2 p01 = __half22float2(h2exp2(__floats2half2_rn(y0, y1)));
      float2 p23 = __half22float2(h2exp2(__floats2half2_rn(y2, y3)));
      float p0 = p01.x, p1 = p01.y, p2 = p23.x, p3 = p23.y;
      ps0 += p0 + p1; ps1 += p2 + p3;
      __nv_bfloat162 h, l;
      split2(p0, p1, h, l);
      pkh[j][0] = *(uint32_t*)&h; pkl[j][0] = *(uint32_t*)&l;
      split2(p2, p3, h, l);
      pkh[j][1] = *(uint32_t*)&h; pkl[j][1] = *(uint32_t*)&l;
    }
    ps0 += __shfl_xor_sync(0xffffffffu, ps0, 1);
    ps0 += __shfl_xor_sync(0xffffffffu, ps0, 2);
    ps1 += __shfl_xor_sync(0xffffffffu, ps1, 1);
    ps1 += __shfl_xor_sync(0xffffffffu, ps1, 2);
    l0 = l0 * s0f + ps0;
    l1 = l1 * s1f + ps1;
#pragma unroll
    for (int nt = 0; nt < 16; nt++) {
      ctxf[nt][0] *= s0f; ctxf[nt][1] *= s0f;
      ctxf[nt][2] *= s1f; ctxf[nt][3] *= s1f;
    }

    // ---- P·V (3-term) ----
#pragma unroll
    for (int k0 = 0; k0 < 4; k0++) {
      uint32_t aH[4] = {pkh[2 * k0][0], pkh[2 * k0][1],
                        pkh[2 * k0 + 1][0], pkh[2 * k0 + 1][1]};
      uint32_t aL[4] = {pkl[2 * k0][0], pkl[2 * k0][1],
                        pkl[2 * k0 + 1][0], pkl[2 * k0 + 1][1]};
      const int mI = lane >> 3, iI = lane & 7;
      const int keyr = k0 * 16 + iI + (mI & 1) * 8;
#pragma unroll
      for (int nn = 0; nn < 8; nn++) {
        int dstart = nn * 16 + (mI >> 1) * 8;
        uint32_t voff = (uint32_t)(dstart >> 6) * 8192 + (uint32_t)keyr * 128 +
            (((uint32_t)(dstart & 63) * 2) ^ ((uint32_t)(keyr & 7) << 4));
        uint32_t bh[4], bl[4];
        ldsm4t(bh, Vh + voff);
        ldsm4t(bl, Vl + voff);
        mma16816(ctxf[2 * nn], aH, bh[0], bh[1]);
        mma16816(ctxf[2 * nn], aH, bl[0], bl[1]);
        mma16816(ctxf[2 * nn], aL, bh[0], bh[1]);
        mma16816(ctxf[2 * nn + 1], aH, bh[2], bh[3]);
        mma16816(ctxf[2 * nn + 1], aH, bl[2], bl[3]);
        mma16816(ctxf[2 * nn + 1], aL, bh[2], bh[3]);
      }
    }
    __syncthreads();
    if (c + 3 < nch) issue_kv(c + 3, stage);
  }

  // ---- epilogue: write bf16 hi/lo ctx directly ----
  const float il0 = 1.f / l0, il1 = 1.f / l1;
  const int tq0 = t0 + (r0 >> 2), tq1 = t0 + ((r0 + 8) >> 2);
  const int h = (kv << 2) + (r0 & 3);
  size_t o0 = (((size_t)b * T_ + tq0) * HQ + h) * (size_t)D_;
  size_t o1 = (((size_t)b * T_ + tq1) * HQ + h) * (size_t)D_;
#pragma unroll
  for (int nt = 0; nt < 16; nt++) {
    int d = nt * 8 + 2 * (lane & 3);
    __nv_bfloat162 hh, ll;
    split2(ctxf[nt][0] * il0, ctxf[nt][1] * il0, hh, ll);
    cth[(o0 + d) >> 1] = hh; ctl[(o0 + d) >> 1] = ll;
    split2(ctxf[nt][2] * il1, ctxf[nt][3] * il1, hh, ll);
    cth[(o1 + d) >> 1] = hh; ctl[(o1 + d) >> 1] = ll;
  }
}

// ---------------------------------------------------------------------------
// kernel_launch
// ---------------------------------------------------------------------------
extern "C" void kernel_launch(void* const* d_in, const int* in_sizes, int n_in,
                              void* d_out, int out_size) {
  const float* x  = (const float*)d_in[0];
  const int*   sp = (const int*)  d_in[1];
  const float* ck = (const float*)d_in[2];
  const float* cv = (const float*)d_in[3];
  const float* Wq = (const float*)d_in[4];
  const float* Wk = (const float*)d_in[5];
  const float* Wv = (const float*)d_in[6];
  const float* Wo = (const float*)d_in[7];
  float* out = (float*)d_out;

  constexpr int GEMM_SMEM = 131072;
  constexpr int ATTN_SMEM = 32768 + 3 * 65536;  // 224KB

  static float *qkvb;
  static __nv_bfloat16 *xh, *xl, *wqkvh, *wqkvl, *woh, *wol,
      *cth, *ctl, *qah, *qal, *kch, *kcl, *vch, *vcl;
  static bool init_done = false;
  if (!init_done) {
    cudaGetSymbolAddress((void**)&qkvb, g_qkv);
    cudaGetSymbolAddress((void**)&xh, g_xh);
    cudaGetSymbolAddress((void**)&xl, g_xl);
    cudaGetSymbolAddress((void**)&wqkvh, g_wqkvh);
    cudaGetSymbolAddress((void**)&wqkvl, g_wqkvl);
    cudaGetSymbolAddress((void**)&woh, g_woh);
    cudaGetSymbolAddress((void**)&wol, g_wol);
    cudaGetSymbolAddress((void**)&cth, g_cth);
    cudaGetSymbolAddress((void**)&ctl, g_ctl);
    cudaGetSymbolAddress((void**)&qah, g_qah);
    cudaGetSymbolAddress((void**)&qal, g_qal);
    cudaGetSymbolAddress((void**)&kch, g_kch);
    cudaGetSymbolAddress((void**)&kcl, g_kcl);
    cudaGetSymbolAddress((void**)&vch, g_vch);
    cudaGetSymbolAddress((void**)&vcl, g_vcl);
    cudaFuncSetAttribute(gemm_mma_kernel,
                         cudaFuncAttributeMaxDynamicSharedMemorySize, GEMM_SMEM);
    cudaFuncSetAttribute(attn_mma_kernel,
                         cudaFuncAttributeMaxDynamicSharedMemorySize, ATTN_SMEM);
    init_done = true;
  }

  const int M = B_ * T_;  // 2048

  // fp32 -> bf16 hi/lo conversions: x, fused W_qkv, Wo
  const int n4x = M * C_ / 4;
  const int n4q = C_ * C_ / 4;
  const int n4k = HKV * D_ * C_ / 4;
  const size_t kofs = (size_t)C_ * C_;          // elements
  const size_t vofs = kofs + (size_t)HKV * D_ * C_;
  cvt_kernel<<<(n4x + 255) / 256, 256>>>((const float4*)x,
      (__nv_bfloat162*)xh, (__nv_bfloat162*)xl, n4x);
  cvt_kernel<<<(n4q + 255) / 256, 256>>>((const float4*)Wq,
      (__nv_bfloat162*)wqkvh, (__nv_bfloat162*)wqkvl, n4q);
  cvt_kernel<<<(n4k + 255) / 256, 256>>>((const float4*)Wk,
      (__nv_bfloat162*)(wqkvh + kofs), (__nv_bfloat162*)(wqkvl + kofs), n4k);
  cvt_kernel<<<(n4k + 255) / 256, 256>>>((const float4*)Wv,
      (__nv_bfloat162*)(wqkvh + vofs), (__nv_bfloat162*)(wqkvl + vofs), n4k);
  cvt_kernel<<<(n4q + 255) / 256, 256>>>((const float4*)Wo,
      (__nv_bfloat162*)woh, (__nv_bfloat162*)wol, n4q);

  // Fused QKV projection: C[M, 6144]
  gemm_mma_kernel<<<dim3(NQKV / 128, M / 128), 256, GEMM_SMEM>>>(
      xh, xl, wqkvh, wqkvl, qkvb, M, NQKV, C_);

  // Fused rope + split + pack (fresh) and cache pack
  const int fpairs = M * HQ * 64 + 2 * M * HKV * 64;
  rope_pack_kernel<<<(fpairs + 255) / 256, 256>>>(qkvb, sp,
      (__nv_bfloat162*)qah, (__nv_bfloat162*)qal,
      (__nv_bfloat162*)kch, (__nv_bfloat162*)kcl,
      (__nv_bfloat162*)vch, (__nv_bfloat162*)vcl);
  const int npack = B_ * CT_ * HKV * (D_ / 4);
  pack_cache_kernel<<<(npack + 255) / 256, 256>>>(ck, cv, sp,
      (__nv_bfloat162*)kch, (__nv_bfloat162*)kcl,
      (__nv_bfloat162*)vch, (__nv_bfloat162*)vcl);

  // HMMA flash attention -> bf16 hi/lo ctx
  attn_mma_kernel<<<dim3(T_ / 32, HKV, B_), 256, ATTN_SMEM>>>(
      qah, qal, kch, kcl, vch, vcl, sp,
      (__nv_bfloat162*)cth, (__nv_bfloat162*)ctl);

  // Output projection
  gemm_mma_kernel<<<dim3(C_ / 128, M / 128), 256, GEMM_SMEM>>>(
      cth, ctl, woh, wol, out, M, C_, C_);
}

// round 15
// speedup vs baseline: 1.5396x; 1.5396x over previous
#include <cuda_runtime.h>
#include <cuda_bf16.h>
#include <cuda_fp16.h>
#include <cstdint>
#include <math.h>

// Problem constants
constexpr int B_   = 2;
constexpr int T_   = 1024;
constexpr int C_   = 4096;
constexpr int HQ   = 32;
constexpr int HKV  = 8;
constexpr int D_   = 128;
constexpr int G_   = 4;
constexpr int CT_  = 4096;
constexpr int NQKV = C_ + 2 * HKV * D_;  // 6144

// fp32 scratch: fused qkv output [M, 6144]
__device__ float g_qkv[(size_t)B_ * T_ * NQKV];

// fp16 operands: A-sides single, B-sides (weights) hi/lo
__device__ __half g_xh  [(size_t)B_ * T_ * C_];
__device__ __half g_wqkvh[(size_t)NQKV * C_];
__device__ __half g_wqkvl[(size_t)NQKV * C_];
__device__ __half g_woh [(size_t)C_ * C_];
__device__ __half g_wol [(size_t)C_ * C_];
__device__ __half g_cth [(size_t)B_ * T_ * C_];

// fp16 attention operands: Q single, K/V hi/lo
__device__ __half g_qah[(size_t)B_ * T_ * HQ * D_];
__device__ __half g_kch[(size_t)B_ * CT_ * HKV * D_];
__device__ __half g_kcl[(size_t)B_ * CT_ * HKV * D_];
__device__ __half g_vch[(size_t)B_ * CT_ * HKV * D_];
__device__ __half g_vcl[(size_t)B_ * CT_ * HKV * D_];

__device__ __forceinline__ uint32_t smem_u32(const void* p) {
  uint32_t a;
  asm("{ .reg .u64 t; cvta.to.shared.u64 t, %1; cvt.u32.u64 %0, t; }"
      : "=r"(a) : "l"(p));
  return a;
}

__device__ __forceinline__ void ldsm4(uint32_t* r, uint32_t addr) {
  asm volatile("ldmatrix.sync.aligned.m8n8.x4.shared.b16 {%0,%1,%2,%3}, [%4];"
               : "=r"(r[0]), "=r"(r[1]), "=r"(r[2]), "=r"(r[3]) : "r"(addr));
}

__device__ __forceinline__ void ldsm4t(uint32_t* r, uint32_t addr) {
  asm volatile("ldmatrix.sync.aligned.m8n8.x4.trans.shared.b16 {%0,%1,%2,%3}, [%4];"
               : "=r"(r[0]), "=r"(r[1]), "=r"(r[2]), "=r"(r[3]) : "r"(addr));
}

// fp16 x fp16 -> fp32 accum
__device__ __forceinline__ void mma16816h(float* d, const uint32_t* a,
                                          uint32_t b0, uint32_t b1) {
  asm volatile(
      "mma.sync.aligned.m16n8k16.row.col.f32.f16.f16.f32 "
      "{%0,%1,%2,%3},{%4,%5,%6,%7},{%8,%9},{%0,%1,%2,%3};"
      : "+f"(d[0]), "+f"(d[1]), "+f"(d[2]), "+f"(d[3])
      : "r"(a[0]), "r"(a[1]), "r"(a[2]), "r"(a[3]), "r"(b0), "r"(b1));
}

__device__ __forceinline__ void cp_async16(uint32_t dst, const void* src) {
  asm volatile("cp.async.cg.shared.global [%0], [%1], 16;"
               :: "r"(dst), "l"(src) : "memory");
}

__device__ __forceinline__ void split2h(float a0, float a1, __half2& h,
                                        __half2& l) {
  h = __floats2half2_rn(a0, a1);
  float2 hf = __half22float2(h);
  l = __floats2half2_rn(a0 - hf.x, a1 - hf.y);
}

// ---------------------------------------------------------------------------
// fp32 -> fp16 single (for A-side operands)
// ---------------------------------------------------------------------------
__global__ void cvt1_kernel(const float4* __restrict__ in,
                            __half2* __restrict__ hi, int n4) {
  int i = blockIdx.x * blockDim.x + threadIdx.x;
  if (i >= n4) return;
  float4 v = in[i];
  hi[2 * i]     = __floats2half2_rn(v.x, v.y);
  hi[2 * i + 1] = __floats2half2_rn(v.z, v.w);
}

// ---------------------------------------------------------------------------
// fp32 -> fp16 hi/lo (for B-side operands; residual may be subnormal - OK)
// ---------------------------------------------------------------------------
__global__ void cvt2_kernel(const float4* __restrict__ in,
                            __half2* __restrict__ hi,
                            __half2* __restrict__ lo, int n4) {
  int i = blockIdx.x * blockDim.x + threadIdx.x;
  if (i >= n4) return;
  float4 v = in[i];
  __half2 h0, l0, h1, l1;
  split2h(v.x, v.y, h0, l0);
  split2h(v.z, v.w, h1, l1);
  hi[2 * i] = h0; hi[2 * i + 1] = h1;
  lo[2 * i] = l0; lo[2 * i + 1] = l1;
}

// ---------------------------------------------------------------------------
// Fused rope + pack: q -> fp16 single; k -> fp16 hi/lo at s=sp+t; v likewise.
// ---------------------------------------------------------------------------
__global__ void rope_pack_kernel(const float* __restrict__ qkv,
                                 const int* __restrict__ spp,
                                 __half2* __restrict__ qh,
                                 __half2* __restrict__ kh,
                                 __half2* __restrict__ kl,
                                 __half2* __restrict__ vh,
                                 __half2* __restrict__ vl) {
  const int sp = *spp;
  const int M = B_ * T_;
  const int qpairs = M * HQ * 64;
  const int kpairs = M * HKV * 64;
  int idx = blockIdx.x * blockDim.x + threadIdx.x;

  if (idx < qpairs) {
    const int i = idx & 63, h = (idx >> 6) & 31, m = idx >> 11;
    const int t = m % T_;
    const float freq = __expf(-(float)i * (9.210340371976184f / 64.f));
    float s, c;
    sincosf((float)(sp + t) * freq, &s, &c);
    float2 x = *(const float2*)(qkv + (size_t)m * NQKV + h * D_ + 2 * i);
    qh[idx] = __floats2half2_rn(x.x * c - x.y * s, x.x * s + x.y * c);
    return;
  }
  idx -= qpairs;
  if (idx < kpairs) {
    const int i = idx & 63, kv = (idx >> 6) & 7, m = idx >> 9;
    const int t = m % T_, b = m / T_;
    const float freq = __expf(-(float)i * (9.210340371976184f / 64.f));
    float s, c;
    sincosf((float)(sp + t) * freq, &s, &c);
    float2 x = *(const float2*)(qkv + (size_t)m * NQKV + C_ + kv * D_ + 2 * i);
    float o0 = x.x * c - x.y * s, o1 = x.x * s + x.y * c;
    __half2 hh, ll;
    split2h(o0, o1, hh, ll);
    size_t dst = (((size_t)b * CT_ + sp + t) * HKV + kv) * 64 + i;
    kh[dst] = hh; kl[dst] = ll;
    return;
  }
  idx -= kpairs;
  if (idx >= kpairs) return;
  const int i = idx & 63, kv = (idx >> 6) & 7, m = idx >> 9;
  const int t = m % T_, b = m / T_;
  float2 x = *(const float2*)(qkv + (size_t)m * NQKV + C_ + HKV * D_ + kv * D_ + 2 * i);
  __half2 hh, ll;
  split2h(x.x, x.y, hh, ll);
  size_t dst = (((size_t)b * CT_ + sp + t) * HKV + kv) * 64 + i;
  vh[dst] = hh; vl[dst] = ll;
}

// ---------------------------------------------------------------------------
// Pack cache K/V (s < sp) -> fp16 hi/lo concat buffers.
// ---------------------------------------------------------------------------
__global__ void pack_cache_kernel(const float* __restrict__ ck,
                                  const float* __restrict__ cv,
                                  const int* __restrict__ spp,
                                  __half2* __restrict__ kh,
                                  __half2* __restrict__ kl,
                                  __half2* __restrict__ vh,
                                  __half2* __restrict__ vl) {
  const int sp = *spp;
  int idx = blockIdx.x * blockDim.x + threadIdx.x;
  int d4 = idx & 31;
  int kv = (idx >> 5) & 7;
  int s  = (idx >> 8) & (CT_ - 1);
  int b  = idx >> 20;
  if (b >= B_ || s >= sp) return;

  size_t src = (((size_t)b * CT_ + s) * HKV + kv) * D_ + d4 * 4;
  size_t dst2 = ((((size_t)b * CT_ + s) * HKV + kv) * D_) / 2 + d4 * 2;

  float4 kx = *(const float4*)(ck + src);
  float4 vx = *(const float4*)(cv + src);
  __half2 h, l;
  split2h(kx.x, kx.y, h, l); kh[dst2] = h; kl[dst2] = l;
  split2h(kx.z, kx.w, h, l); kh[dst2 + 1] = h; kl[dst2 + 1] = l;
  split2h(vx.x, vx.y, h, l); vh[dst2] = h; vl[dst2] = l;
  split2h(vx.z, vx.w, h, l); vh[dst2 + 1] = h; vl[dst2 + 1] = l;
}

// ---------------------------------------------------------------------------
// fp16 2-term GEMM: C[M,N] = A[M,K]*B[N,K]^T, A single fp16, B hi/lo fp16.
// 128x128 tile, BK=64, 256 threads, 8 warps (2x4). smem: 2 x 48KB.
// ---------------------------------------------------------------------------
__global__ void __launch_bounds__(256) gemm_mma_kernel(
    const __half* __restrict__ Ah, const __half* __restrict__ Bh,
    const __half* __restrict__ Bl, float* __restrict__ C, int M, int N, int K) {
  extern __shared__ char sm[];
  const int tid = threadIdx.x, lane = tid & 31, wid = tid >> 5;
  const int bm = blockIdx.y << 7, bn = blockIdx.x << 7;
  const uint32_t sbase = smem_u32(sm);

  const int warp_m = wid >> 2;
  const int warp_n = wid & 3;

  const __half* srcs[3] = {Ah, Bh, Bl};

  auto issue = [&](int c, int buf) {
    const int k0 = c << 6;
    const int r = tid >> 1;
    const int s0 = (tid & 1) << 2;
#pragma unroll
    for (int m = 0; m < 3; m++) {
      const __half* g = srcs[m] + (size_t)((m < 1 ? bm : bn) + r) * K + k0;
      uint32_t dstb = sbase + buf * 49152 + m * 16384 + r * 128;
      uint32_t rsw = (uint32_t)(r & 7) << 4;
#pragma unroll
      for (int i = 0; i < 4; i++) {
        int seg = s0 + i;
        cp_async16(dstb + ((uint32_t)(seg << 4) ^ rsw), g + seg * 8);
      }
    }
    asm volatile("cp.async.commit_group;" ::: "memory");
  };

  float acc[4][4][4];
#pragma unroll
  for (int i = 0; i < 4; i++)
#pragma unroll
    for (int j = 0; j < 4; j++)
#pragma unroll
      for (int t = 0; t < 4; t++) acc[i][j][t] = 0.f;

  const int l7 = lane & 7, m1b = (lane >> 3) & 1, m2b = lane >> 4;

  const int nch = K >> 6;
  issue(0, 0);
  for (int c = 0; c < nch; c++) {
    const int buf = c & 1;
    if (c + 1 < nch) {
      issue(c + 1, buf ^ 1);
      asm volatile("cp.async.wait_group 1;" ::: "memory");
    } else {
      asm volatile("cp.async.wait_group 0;" ::: "memory");
    }
    __syncthreads();

    const uint32_t bA  = sbase + buf * 49152;
    const uint32_t bBh = bA + 16384;
    const uint32_t bBl = bA + 32768;

#pragma unroll
    for (int kk = 0; kk < 4; kk++) {
      uint32_t ah[4][4], bh[2][4], bl[2][4];
#pragma unroll
      for (int i = 0; i < 4; i++) {
        int row = warp_m * 64 + i * 16 + l7 + m1b * 8;
        uint32_t bo = (uint32_t)(kk * 32 + m2b * 16) ^ ((uint32_t)(row & 7) << 4);
        ldsm4(ah[i], bA + (uint32_t)row * 128 + bo);
      }
#pragma unroll
      for (int jp = 0; jp < 2; jp++) {
        int row = warp_n * 32 + jp * 16 + l7 + m2b * 8;
        uint32_t bo = (uint32_t)(kk * 32 + m1b * 16) ^ ((uint32_t)(row & 7) << 4);
        uint32_t ro = (uint32_t)row * 128 + bo;
        ldsm4(bh[jp], bBh + ro);
        ldsm4(bl[jp], bBl + ro);
      }
#pragma unroll
      for (int i = 0; i < 4; i++) {
#pragma unroll
        for (int j = 0; j < 4; j++) {
          uint32_t h0 = bh[j >> 1][(j & 1) * 2], h1 = bh[j >> 1][(j & 1) * 2 + 1];
          uint32_t l0 = bl[j >> 1][(j & 1) * 2], l1 = bl[j >> 1][(j & 1) * 2 + 1];
          mma16816h(acc[i][j], ah[i], h0, h1);
          mma16816h(acc[i][j], ah[i], l0, l1);
        }
      }
    }
    __syncthreads();
  }

  const int rq = lane >> 2, cq = (lane & 3) << 1;
#pragma unroll
  for (int i = 0; i < 4; i++) {
#pragma unroll
    for (int j = 0; j < 4; j++) {
      int row0 = bm + warp_m * 64 + i * 16 + rq;
      int col = bn + warp_n * 32 + j * 8 + cq;
      *(float2*)(C + (size_t)row0 * N + col) =
          make_float2(acc[i][j][0], acc[i][j][1]);
      *(float2*)(C + (size_t)(row0 + 8) * N + col) =
          make_float2(acc[i][j][2], acc[i][j][3]);
    }
  }
}

// ---------------------------------------------------------------------------
// fp16 2-term HMMA flash attention. Q single fp16 (32KB smem), K/V hi/lo,
// 2-stage cp.async (2 x 64KB). P = h2exp2 half2 used directly as A-fragment
// (matches the normalizer exactly). ctx written as fp16 single.
// smem = 32KB + 128KB = 160KB.
// ---------------------------------------------------------------------------
__global__ void __launch_bounds__(256) attn_mma_kernel(
    const __half* __restrict__ qh_, const __half* __restrict__ kh_,
    const __half* __restrict__ kl_, const __half* __restrict__ vh_,
    const __half* __restrict__ vl_, const int* __restrict__ spp,
    __half2* __restrict__ cth) {
  extern __shared__ __align__(1024) char sm[];
  const int sp = *spp;
  const int Stot = sp + T_;
  const int tid = threadIdx.x, lane = tid & 31, w = tid >> 5;
  const int t0 = (gridDim.x - 1 - blockIdx.x) << 5;  // heavy-first
  const int kv = blockIdx.y;
  const int b  = blockIdx.z;
  const uint32_t sb = smem_u32(sm);
  const uint32_t QB = sb;                 // 32KB (2 panels x 16KB)
  const uint32_t KV0 = sb + 32768;        // 2 x 64KB

  // Load Q tile (128 rows x 128 d fp16)
#pragma unroll
  for (int it = 0; it < 8; it++) {
    int idx = it * 256 + tid;
    int row = idx >> 4, seg = idx & 15;
    int t = t0 + (row >> 2), h = (kv << 2) + (row & 3);
    const __half* src = qh_ + (((size_t)b * T_ + t) * HQ + h) * D_ + seg * 8;
    uint32_t dst = QB + (seg >> 3) * 16384 + (uint32_t)row * 128 +
        (((uint32_t)(seg & 7) << 4) ^ ((uint32_t)(row & 7) << 4));
    cp_async16(dst, src);
  }
  asm volatile("cp.async.commit_group;" ::: "memory");

  const __half* kvsrc[4] = {kh_, kl_, vh_, vl_};
  auto issue_kv = [&](int c, int buf) {
    const uint32_t base = KV0 + (uint32_t)buf * 65536;
#pragma unroll
    for (int it = 0; it < 16; it++) {
      int idx = it * 256 + tid;
      int mat = idx >> 10, rem = idx & 1023;
      int row = rem >> 4, seg = rem & 15;
      int s = c * 64 + row;
      if (s > Stot - 1) s = Stot - 1;
      const __half* g = kvsrc[mat] +
          (((size_t)b * CT_ + s) * HKV + kv) * D_ + seg * 8;
      uint32_t dst = base + mat * 16384 + (seg >> 3) * 8192 + (uint32_t)row * 128 +
          (((uint32_t)(seg & 7) << 4) ^ ((uint32_t)(row & 7) << 4));
      cp_async16(dst, g);
    }
    asm volatile("cp.async.commit_group;" ::: "memory");
  };

  float ctxf[16][4];
#pragma unroll
  for (int i = 0; i < 16; i++)
#pragma unroll
    for (int j = 0; j < 4; j++) ctxf[i][j] = 0.f;
  float m0 = -1e30f, m1 = -1e30f, l0 = 0.f, l1 = 0.f;

  const int wbase = w * 16;
  const int l7 = lane & 7, m1b = (lane >> 3) & 1, m2b = lane >> 4;
  const int r0 = wbase + (lane >> 2);
  const int lim0 = sp + t0 + (r0 >> 2);
  const int lim1 = sp + t0 + ((r0 + 8) >> 2);
  const float scale = 0.08838834764831845f;
  const float L2E = 1.4426950408889634f;
  const int arow = wbase + l7 + m1b * 8;

  const int nch = (sp + t0 + 31) / 64 + 1;
  issue_kv(0, 0);
  for (int c = 0; c < nch; c++) {
    const int buf = c & 1;
    if (c + 1 < nch) {
      issue_kv(c + 1, buf ^ 1);
      asm volatile("cp.async.wait_group 1;" ::: "memory");
    } else {
      asm volatile("cp.async.wait_group 0;" ::: "memory");
    }
    __syncthreads();

    const uint32_t Kh = KV0 + (uint32_t)buf * 65536, Kl = Kh + 16384;
    const uint32_t Vh = Kh + 32768, Vl = Kh + 49152;

    // ---- QK^T (2-term: Q single, K hi/lo) ----
    float sc[8][4];
#pragma unroll
    for (int j = 0; j < 8; j++)
#pragma unroll
      for (int e = 0; e < 4; e++) sc[j][e] = 0.f;

#pragma unroll
    for (int kk = 0; kk < 8; kk++) {
      uint32_t abo = ((uint32_t)((kk & 3) * 32 + m2b * 16)) ^
                     ((uint32_t)(arow & 7) << 4);
      uint32_t aoff = (uint32_t)(kk >> 2) * 16384 + (uint32_t)arow * 128 + abo;
      uint32_t qa[4];
      ldsm4(qa, QB + aoff);
#pragma unroll
      for (int jp = 0; jp < 4; jp++) {
        int brow = jp * 16 + l7 + m2b * 8;
        uint32_t bbo = ((uint32_t)((kk & 3) * 32 + m1b * 16)) ^
                       ((uint32_t)(brow & 7) << 4);
        uint32_t boff = (uint32_t)(kk >> 2) * 8192 + (uint32_t)brow * 128 + bbo;
        uint32_t bh[4], bl[4];
        ldsm4(bh, Kh + boff);
        ldsm4(bl, Kl + boff);
        mma16816h(sc[jp * 2], qa, bh[0], bh[1]);
        mma16816h(sc[jp * 2], qa, bl[0], bl[1]);
        mma16816h(sc[jp * 2 + 1], qa, bh[2], bh[3]);
        mma16816h(sc[jp * 2 + 1], qa, bl[2], bl[3]);
      }
    }

    // ---- mask + online softmax ----
    const int kbase = c * 64;
    float cm0 = -1e30f, cm1 = -1e30f;
#pragma unroll
    for (int j = 0; j < 8; j++) {
#pragma unroll
      for (int e = 0; e < 2; e++) {
        int key = kbase + j * 8 + 2 * (lane & 3) + e;
        float v0 = sc[j][e] * scale;
        float v1 = sc[j][2 + e] * scale;
        if (key > lim0) v0 = -1e30f;
        if (key > lim1) v1 = -1e30f;
        sc[j][e] = v0; sc[j][2 + e] = v1;
        cm0 = fmaxf(cm0, v0); cm1 = fmaxf(cm1, v1);
      }
    }
    cm0 = fmaxf(cm0, __shfl_xor_sync(0xffffffffu, cm0, 1));
    cm0 = fmaxf(cm0, __shfl_xor_sync(0xffffffffu, cm0, 2));
    cm1 = fmaxf(cm1, __shfl_xor_sync(0xffffffffu, cm1, 1));
    cm1 = fmaxf(cm1, __shfl_xor_sync(0xffffffffu, cm1, 2));
    float mn0 = fmaxf(m0, cm0), mn1 = fmaxf(m1, cm1);
    float s0f = __expf(m0 - mn0), s1f = __expf(m1 - mn1);
    m0 = mn0; m1 = mn1;
    const float m0L = m0 * L2E, m1L = m1 * L2E;

    float ps0 = 0.f, ps1 = 0.f;
    uint32_t pk[8][2];  // fp16x2 probs: [j][0] rows r, [j][1] rows r+8
#pragma unroll
    for (int j = 0; j < 8; j++) {
      float y0 = fmaf(sc[j][0], L2E, -m0L), y1 = fmaf(sc[j][1], L2E, -m0L);
      float y2 = fmaf(sc[j][2], L2E, -m1L), y3 = fmaf(sc[j][3], L2E, -m1L);
      __half2 p01 = h2exp2(__floats2half2_rn(y0, y1));
      __half2 p23 = h2exp2(__floats2half2_rn(y2, y3));
      pk[j][0] = *(uint32_t*)&p01;
      pk[j][1] = *(uint32_t*)&p23;
      float2 f01 = __half22float2(p01), f23 = __half22float2(p23);
      ps0 += f01.x + f01.y; ps1 += f23.x + f23.y;
    }
    ps0 += __shfl_xor_sync(0xffffffffu, ps0, 1);
    ps0 += __shfl_xor_sync(0xffffffffu, ps0, 2);
    ps1 += __shfl_xor_sync(0xffffffffu, ps1, 1);
    ps1 += __shfl_xor_sync(0xffffffffu, ps1, 2);
    l0 = l0 * s0f + ps0;
    l1 = l1 * s1f + ps1;
#pragma unroll
    for (int nt = 0; nt < 16; nt++) {
      ctxf[nt][0] *= s0f; ctxf[nt][1] *= s0f;
      ctxf[nt][2] *= s1f; ctxf[nt][3] *= s1f;
    }

    // ---- P·V (2-term: P exact fp16, V hi/lo) ----
#pragma unroll
    for (int k0 = 0; k0 < 4; k0++) {
      uint32_t aP[4] = {pk[2 * k0][0], pk[2 * k0][1],
                        pk[2 * k0 + 1][0], pk[2 * k0 + 1][1]};
      const int mI = lane >> 3, iI = lane & 7;
      const int keyr = k0 * 16 + iI + (mI & 1) * 8;
#pragma unroll
      for (int nn = 0; nn < 8; nn++) {
        int dstart = nn * 16 + (mI >> 1) * 8;
        uint32_t voff = (uint32_t)(dstart >> 6) * 8192 + (uint32_t)keyr * 128 +
            (((uint32_t)(dstart & 63) * 2) ^ ((uint32_t)(keyr & 7) << 4));
        uint32_t bh[4], bl[4];
        ldsm4t(bh, Vh + voff);
        ldsm4t(bl, Vl + voff);
        mma16816h(ctxf[2 * nn], aP, bh[0], bh[1]);
        mma16816h(ctxf[2 * nn], aP, bl[0], bl[1]);
        mma16816h(ctxf[2 * nn + 1], aP, bh[2], bh[3]);
        mma16816h(ctxf[2 * nn + 1], aP, bl[2], bl[3]);
      }
    }
    __syncthreads();
  }

  // ---- epilogue: write fp16 ctx ----
  const float il0 = 1.f / l0, il1 = 1.f / l1;
  const int tq0 = t0 + (r0 >> 2), tq1 = t0 + ((r0 + 8) >> 2);
  const int h = (kv << 2) + (r0 & 3);
  size_t o0 = (((size_t)b * T_ + tq0) * HQ + h) * (size_t)D_;
  size_t o1 = (((size_t)b * T_ + tq1) * HQ + h) * (size_t)D_;
#pragma unroll
  for (int nt = 0; nt < 16; nt++) {
    int d = nt * 8 + 2 * (lane & 3);
    cth[(o0 + d) >> 1] = __floats2half2_rn(ctxf[nt][0] * il0, ctxf[nt][1] * il0);
    cth[(o1 + d) >> 1] = __floats2half2_rn(ctxf[nt][2] * il1, ctxf[nt][3] * il1);
  }
}

// ---------------------------------------------------------------------------
// kernel_launch
// ---------------------------------------------------------------------------
extern "C" void kernel_launch(void* const* d_in, const int* in_sizes, int n_in,
                              void* d_out, int out_size) {
  const float* x  = (const float*)d_in[0];
  const int*   sp = (const int*)  d_in[1];
  const float* ck = (const float*)d_in[2];
  const float* cv = (const float*)d_in[3];
  const float* Wq = (const float*)d_in[4];
  const float* Wk = (const float*)d_in[5];
  const float* Wv = (const float*)d_in[6];
  const float* Wo = (const float*)d_in[7];
  float* out = (float*)d_out;

  constexpr int GEMM_SMEM = 98304;   // 2 x 48KB
  constexpr int ATTN_SMEM = 163840;  // 32KB Q + 2 x 64KB KV

  static float *qkvb;
  static __half *xh, *wqkvh, *wqkvl, *woh, *wol, *cth, *qah,
      *kch, *kcl, *vch, *vcl;
  static bool init_done = false;
  if (!init_done) {
    cudaGetSymbolAddress((void**)&qkvb, g_qkv);
    cudaGetSymbolAddress((void**)&xh, g_xh);
    cudaGetSymbolAddress((void**)&wqkvh, g_wqkvh);
    cudaGetSymbolAddress((void**)&wqkvl, g_wqkvl);
    cudaGetSymbolAddress((void**)&woh, g_woh);
    cudaGetSymbolAddress((void**)&wol, g_wol);
    cudaGetSymbolAddress((void**)&cth, g_cth);
    cudaGetSymbolAddress((void**)&qah, g_qah);
    cudaGetSymbolAddress((void**)&kch, g_kch);
    cudaGetSymbolAddress((void**)&kcl, g_kcl);
    cudaGetSymbolAddress((void**)&vch, g_vch);
    cudaGetSymbolAddress((void**)&vcl, g_vcl);
    cudaFuncSetAttribute(gemm_mma_kernel,
                         cudaFuncAttributeMaxDynamicSharedMemorySize, GEMM_SMEM);
    cudaFuncSetAttribute(attn_mma_kernel,
                         cudaFuncAttributeMaxDynamicSharedMemorySize, ATTN_SMEM);
    init_done = true;
  }

  const int M = B_ * T_;  // 2048

  // Conversions: x -> fp16 single; weights -> fp16 hi/lo
  const int n4x = M * C_ / 4;
  const int n4q = C_ * C_ / 4;
  const int n4k = HKV * D_ * C_ / 4;
  const size_t kofs = (size_t)C_ * C_;
  const size_t vofs = kofs + (size_t)HKV * D_ * C_;
  cvt1_kernel<<<(n4x + 255) / 256, 256>>>((const float4*)x, (__half2*)xh, n4x);
  cvt2_kernel<<<(n4q + 255) / 256, 256>>>((const float4*)Wq,
      (__half2*)wqkvh, (__half2*)wqkvl, n4q);
  cvt2_kernel<<<(n4k + 255) / 256, 256>>>((const float4*)Wk,
      (__half2*)(wqkvh + kofs), (__half2*)(wqkvl + kofs), n4k);
  cvt2_kernel<<<(n4k + 255) / 256, 256>>>((const float4*)Wv,
      (__half2*)(wqkvh + vofs), (__half2*)(wqkvl + vofs), n4k);
  cvt2_kernel<<<(n4q + 255) / 256, 256>>>((const float4*)Wo,
      (__half2*)woh, (__half2*)wol, n4q);

  // Fused QKV projection
  gemm_mma_kernel<<<dim3(NQKV / 128, M / 128), 256, GEMM_SMEM>>>(
      xh, wqkvh, wqkvl, qkvb, M, NQKV, C_);

  // rope + pack fresh; pack cache
  const int fpairs = M * HQ * 64 + 2 * M * HKV * 64;
  rope_pack_kernel<<<(fpairs + 255) / 256, 256>>>(qkvb, sp,
      (__half2*)qah, (__half2*)kch, (__half2*)kcl,
      (__half2*)vch, (__half2*)vcl);
  const int npack = B_ * CT_ * HKV * (D_ / 4);
  pack_cache_kernel<<<(npack + 255) / 256, 256>>>(ck, cv, sp,
      (__half2*)kch, (__half2*)kcl, (__half2*)vch, (__half2*)vcl);

  // Attention -> fp16 ctx
  attn_mma_kernel<<<dim3(T_ / 32, HKV, B_), 256, ATTN_SMEM>>>(
      qah, kch, kcl, vch, vcl, sp, (__half2*)cth);

  // Output projection
  gemm_mma_kernel<<<dim3(C_ / 128, M / 128), 256, GEMM_SMEM>>>(
      cth, woh, wol, out, M, C_, C_);
}